// round 1
// baseline (speedup 1.0000x reference)
#include <cuda_runtime.h>

#define MAXN 8192
#define TEMP 0.07f

// ---- scratch (alloc-free per harness rules) ----
__device__ unsigned g_rowmax[MAXN];
__device__ unsigned g_colmax[MAXN];
__device__ float    g_rowsum[MAXN];
__device__ float    g_colsum[MAXN];
__device__ float    g_diag[MAXN];

// ---- ordered-uint encoding so atomicMax(unsigned) gives float max ----
static __device__ __forceinline__ unsigned encf(float f) {
    unsigned u = __float_as_uint(f);
    return (u & 0x80000000u) ? ~u : (u | 0x80000000u);
}
static __device__ __forceinline__ float decf(unsigned u) {
    return (u & 0x80000000u) ? __uint_as_float(u & 0x7FFFFFFFu)
                             : __uint_as_float(~u);
}

__global__ void init_kernel(int N) {
    int i = blockIdx.x * blockDim.x + threadIdx.x;
    if (i < N) {
        g_rowmax[i] = 0u;   // encodes below any real float (NaN zone) — always overwritten
        g_colmax[i] = 0u;
        g_rowsum[i] = 0.f;
        g_colsum[i] = 0.f;
    }
}

__global__ void diag_kernel(const float* __restrict__ A, const float* __restrict__ B,
                            int N, int E, float invT) {
    int w    = (blockIdx.x * blockDim.x + threadIdx.x) >> 5;
    int lane = threadIdx.x & 31;
    if (w >= N) return;
    float s = 0.f;
    for (int k = lane; k < E; k += 32)
        s += A[(size_t)w * E + k] * B[(size_t)w * E + k];
    #pragma unroll
    for (int o = 16; o > 0; o >>= 1) s += __shfl_xor_sync(0xffffffffu, s, o);
    if (lane == 0) g_diag[w] = s * invT;
}

// PASS 0: masked row/col max of S.   PASS 1: masked shifted-exp row/col sums.
template <int PASS>
__global__ void __launch_bounds__(256, 2)
tile_kernel(const float* __restrict__ A, const float* __restrict__ B,
            const int* __restrict__ fids, int N, int E, float invT) {
    __shared__ float As[16][132];       // +4 pad keeps float4 alignment, trims conflicts
    __shared__ float Bs[16][132];
    __shared__ int   fr[128], fc[128];
    __shared__ float red[128 * 16];
    __shared__ float rm_s[128], cm_s[128];

    const int tid  = threadIdx.x;
    const int tx   = tid & 15, ty = tid >> 4;
    const int row0 = blockIdx.y * 128, col0 = blockIdx.x * 128;

    if (tid < 128) {
        int rr = min(row0 + tid, N - 1);
        int cc = min(col0 + tid, N - 1);
        fr[tid] = fids[rr];
        fc[tid] = fids[cc];
        if (PASS == 1) {
            rm_s[tid] = decf(g_rowmax[rr]);
            cm_s[tid] = decf(g_colmax[cc]);
        }
    }

    float acc[8][8];
    #pragma unroll
    for (int r = 0; r < 8; r++)
        #pragma unroll
        for (int c = 0; c < 8; c++) acc[r][c] = 0.f;

    for (int k0 = 0; k0 < E; k0 += 16) {
        #pragma unroll
        for (int l = 0; l < 2; l++) {
            int idx = tid + l * 256;         // 0..511
            int r   = idx >> 2;              // tile row 0..127
            int k4  = (idx & 3) << 2;        // 0,4,8,12
            int ra  = min(row0 + r, N - 1);
            int rb  = min(col0 + r, N - 1);
            float4 va = *(const float4*)&A[(size_t)ra * E + k0 + k4];
            float4 vb = *(const float4*)&B[(size_t)rb * E + k0 + k4];
            As[k4 + 0][r] = va.x; As[k4 + 1][r] = va.y;
            As[k4 + 2][r] = va.z; As[k4 + 3][r] = va.w;
            Bs[k4 + 0][r] = vb.x; Bs[k4 + 1][r] = vb.y;
            Bs[k4 + 2][r] = vb.z; Bs[k4 + 3][r] = vb.w;
        }
        __syncthreads();
        #pragma unroll
        for (int k = 0; k < 16; k++) {
            float a[8], b[8];
            *(float4*)(a)     = *(const float4*)&As[k][ty * 8];
            *(float4*)(a + 4) = *(const float4*)&As[k][ty * 8 + 4];
            *(float4*)(b)     = *(const float4*)&Bs[k][tx * 8];
            *(float4*)(b + 4) = *(const float4*)&Bs[k][tx * 8 + 4];
            #pragma unroll
            for (int r = 0; r < 8; r++)
                #pragma unroll
                for (int c = 0; c < 8; c++)
                    acc[r][c] = fmaf(a[r], b[c], acc[r][c]);
        }
        __syncthreads();
    }

    if (PASS == 0) {
        float rmx[8], cmx[8];
        #pragma unroll
        for (int r = 0; r < 8; r++) rmx[r] = -3.4e38f;
        #pragma unroll
        for (int c = 0; c < 8; c++) cmx[c] = -3.4e38f;
        #pragma unroll
        for (int r = 0; r < 8; r++) {
            int gr = row0 + ty * 8 + r;
            #pragma unroll
            for (int c = 0; c < 8; c++) {
                int gc = col0 + tx * 8 + c;
                bool valid = (gr < N) && (gc < N) &&
                             ((fr[ty * 8 + r] != fc[tx * 8 + c]) || (gr == gc));
                float s = valid ? acc[r][c] * invT : -3.4e38f;
                rmx[r] = fmaxf(rmx[r], s);
                cmx[c] = fmaxf(cmx[c], s);
            }
        }
        #pragma unroll
        for (int r = 0; r < 8; r++) red[(ty * 8 + r) * 16 + tx] = rmx[r];
        __syncthreads();
        if (tid < 128) {
            float m = red[tid * 16];
            #pragma unroll
            for (int j = 1; j < 16; j++) m = fmaxf(m, red[tid * 16 + j]);
            if (row0 + tid < N) atomicMax(&g_rowmax[row0 + tid], encf(m));
        }
        __syncthreads();
        #pragma unroll
        for (int c = 0; c < 8; c++) red[(tx * 8 + c) * 16 + ty] = cmx[c];
        __syncthreads();
        if (tid < 128) {
            float m = red[tid * 16];
            #pragma unroll
            for (int j = 1; j < 16; j++) m = fmaxf(m, red[tid * 16 + j]);
            if (col0 + tid < N) atomicMax(&g_colmax[col0 + tid], encf(m));
        }
    } else {
        float rsm[8], csm[8];
        #pragma unroll
        for (int r = 0; r < 8; r++) rsm[r] = 0.f;
        #pragma unroll
        for (int c = 0; c < 8; c++) csm[c] = 0.f;
        #pragma unroll
        for (int r = 0; r < 8; r++) {
            int gr = row0 + ty * 8 + r;
            #pragma unroll
            for (int c = 0; c < 8; c++) {
                int gc = col0 + tx * 8 + c;
                bool valid = (gr < N) && (gc < N) &&
                             ((fr[ty * 8 + r] != fc[tx * 8 + c]) || (gr == gc));
                if (valid) {
                    float s = acc[r][c] * invT;
                    rsm[r] += __expf(s - rm_s[ty * 8 + r]);
                    csm[c] += __expf(s - cm_s[tx * 8 + c]);
                }
            }
        }
        #pragma unroll
        for (int r = 0; r < 8; r++) red[(ty * 8 + r) * 16 + tx] = rsm[r];
        __syncthreads();
        if (tid < 128) {
            float sm = 0.f;
            #pragma unroll
            for (int j = 0; j < 16; j++) sm += red[tid * 16 + j];
            if (row0 + tid < N) atomicAdd(&g_rowsum[row0 + tid], sm);
        }
        __syncthreads();
        #pragma unroll
        for (int c = 0; c < 8; c++) red[(tx * 8 + c) * 16 + ty] = csm[c];
        __syncthreads();
        if (tid < 128) {
            float sm = 0.f;
            #pragma unroll
            for (int j = 0; j < 16; j++) sm += red[tid * 16 + j];
            if (col0 + tid < N) atomicAdd(&g_colsum[col0 + tid], sm);
        }
    }
}

__global__ void finalize_kernel(float* out, int N) {
    __shared__ double sb[256];
    double acc = 0.0;
    for (int i = threadIdx.x; i < N; i += 256) {
        float rm = decf(g_rowmax[i]);
        float cm = decf(g_colmax[i]);
        acc += (double)(logf(g_rowsum[i]) + rm +
                        logf(g_colsum[i]) + cm - 2.0f * g_diag[i]);
    }
    sb[threadIdx.x] = acc;
    __syncthreads();
    for (int o = 128; o > 0; o >>= 1) {
        if (threadIdx.x < o) sb[threadIdx.x] += sb[threadIdx.x + o];
        __syncthreads();
    }
    if (threadIdx.x == 0) out[0] = (float)(sb[0] / (double)N);
}

extern "C" void kernel_launch(void* const* d_in, const int* in_sizes, int n_in,
                              void* d_out, int out_size) {
    const float* A    = (const float*)d_in[0];   // audio_embeds [N,E]
    const float* B    = (const float*)d_in[1];   // text_embeds  [N,E]
    const int*   fids = (const int*)d_in[2];     // [N]
    int N = in_sizes[2];
    int E = in_sizes[0] / N;
    float invT = 1.0f / TEMP;

    init_kernel<<<(N + 255) / 256, 256>>>(N);
    diag_kernel<<<(N * 32 + 255) / 256, 256>>>(A, B, N, E, invT);
    dim3 grid((N + 127) / 128, (N + 127) / 128);
    tile_kernel<0><<<grid, 256>>>(A, B, fids, N, E, invT);
    tile_kernel<1><<<grid, 256>>>(A, B, fids, N, E, invT);
    finalize_kernel<<<1, 256>>>((float*)d_out, N);
}

// round 2
// speedup vs baseline: 1.0008x; 1.0008x over previous
#include <cuda_runtime.h>

#define MAXN 8192
#define TEMP 0.07f

// ---- scratch (alloc-free per harness rules) ----
__device__ unsigned g_rowmax[MAXN];
__device__ unsigned g_colmax[MAXN];
__device__ float    g_rowsum[MAXN];
__device__ float    g_colsum[MAXN];
__device__ float    g_diag[MAXN];

// ---- ordered-uint encoding so atomicMax(unsigned) gives float max ----
static __device__ __forceinline__ unsigned encf(float f) {
    unsigned u = __float_as_uint(f);
    return (u & 0x80000000u) ? ~u : (u | 0x80000000u);
}
static __device__ __forceinline__ float decf(unsigned u) {
    return (u & 0x80000000u) ? __uint_as_float(u & 0x7FFFFFFFu)
                             : __uint_as_float(~u);
}

__global__ void init_kernel(int N) {
    int i = blockIdx.x * blockDim.x + threadIdx.x;
    if (i < N) {
        g_rowmax[i] = 0u;   // encodes below any real float (NaN zone) — always overwritten
        g_colmax[i] = 0u;
        g_rowsum[i] = 0.f;
        g_colsum[i] = 0.f;
    }
}

__global__ void diag_kernel(const float* __restrict__ A, const float* __restrict__ B,
                            int N, int E, float invT) {
    int w    = (blockIdx.x * blockDim.x + threadIdx.x) >> 5;
    int lane = threadIdx.x & 31;
    if (w >= N) return;
    float s = 0.f;
    for (int k = lane; k < E; k += 32)
        s += A[(size_t)w * E + k] * B[(size_t)w * E + k];
    #pragma unroll
    for (int o = 16; o > 0; o >>= 1) s += __shfl_xor_sync(0xffffffffu, s, o);
    if (lane == 0) g_diag[w] = s * invT;
}

// PASS 0: masked row/col max of S.   PASS 1: masked shifted-exp row/col sums.
template <int PASS>
__global__ void __launch_bounds__(256, 2)
tile_kernel(const float* __restrict__ A, const float* __restrict__ B,
            const int* __restrict__ fids, int N, int E, float invT) {
    __shared__ float As[16][132];       // +4 pad keeps float4 alignment, trims conflicts
    __shared__ float Bs[16][132];
    __shared__ int   fr[128], fc[128];
    __shared__ float red[128 * 16];
    __shared__ float rm_s[128], cm_s[128];

    const int tid  = threadIdx.x;
    const int tx   = tid & 15, ty = tid >> 4;
    const int row0 = blockIdx.y * 128, col0 = blockIdx.x * 128;

    if (tid < 128) {
        int rr = min(row0 + tid, N - 1);
        int cc = min(col0 + tid, N - 1);
        fr[tid] = fids[rr];
        fc[tid] = fids[cc];
        if (PASS == 1) {
            rm_s[tid] = decf(g_rowmax[rr]);
            cm_s[tid] = decf(g_colmax[cc]);
        }
    }

    float acc[8][8];
    #pragma unroll
    for (int r = 0; r < 8; r++)
        #pragma unroll
        for (int c = 0; c < 8; c++) acc[r][c] = 0.f;

    for (int k0 = 0; k0 < E; k0 += 16) {
        #pragma unroll
        for (int l = 0; l < 2; l++) {
            int idx = tid + l * 256;         // 0..511
            int r   = idx >> 2;              // tile row 0..127
            int k4  = (idx & 3) << 2;        // 0,4,8,12
            int ra  = min(row0 + r, N - 1);
            int rb  = min(col0 + r, N - 1);
            float4 va = *(const float4*)&A[(size_t)ra * E + k0 + k4];
            float4 vb = *(const float4*)&B[(size_t)rb * E + k0 + k4];
            As[k4 + 0][r] = va.x; As[k4 + 1][r] = va.y;
            As[k4 + 2][r] = va.z; As[k4 + 3][r] = va.w;
            Bs[k4 + 0][r] = vb.x; Bs[k4 + 1][r] = vb.y;
            Bs[k4 + 2][r] = vb.z; Bs[k4 + 3][r] = vb.w;
        }
        __syncthreads();
        #pragma unroll
        for (int k = 0; k < 16; k++) {
            float a[8], b[8];
            *(float4*)(a)     = *(const float4*)&As[k][ty * 8];
            *(float4*)(a + 4) = *(const float4*)&As[k][ty * 8 + 4];
            *(float4*)(b)     = *(const float4*)&Bs[k][tx * 8];
            *(float4*)(b + 4) = *(const float4*)&Bs[k][tx * 8 + 4];
            #pragma unroll
            for (int r = 0; r < 8; r++)
                #pragma unroll
                for (int c = 0; c < 8; c++)
                    acc[r][c] = fmaf(a[r], b[c], acc[r][c]);
        }
        __syncthreads();
    }

    if (PASS == 0) {
        float rmx[8], cmx[8];
        #pragma unroll
        for (int r = 0; r < 8; r++) rmx[r] = -3.4e38f;
        #pragma unroll
        for (int c = 0; c < 8; c++) cmx[c] = -3.4e38f;
        #pragma unroll
        for (int r = 0; r < 8; r++) {
            int gr = row0 + ty * 8 + r;
            #pragma unroll
            for (int c = 0; c < 8; c++) {
                int gc = col0 + tx * 8 + c;
                bool valid = (gr < N) && (gc < N) &&
                             ((fr[ty * 8 + r] != fc[tx * 8 + c]) || (gr == gc));
                float s = valid ? acc[r][c] * invT : -3.4e38f;
                rmx[r] = fmaxf(rmx[r], s);
                cmx[c] = fmaxf(cmx[c], s);
            }
        }
        #pragma unroll
        for (int r = 0; r < 8; r++) red[(ty * 8 + r) * 16 + tx] = rmx[r];
        __syncthreads();
        if (tid < 128) {
            float m = red[tid * 16];
            #pragma unroll
            for (int j = 1; j < 16; j++) m = fmaxf(m, red[tid * 16 + j]);
            if (row0 + tid < N) atomicMax(&g_rowmax[row0 + tid], encf(m));
        }
        __syncthreads();
        #pragma unroll
        for (int c = 0; c < 8; c++) red[(tx * 8 + c) * 16 + ty] = cmx[c];
        __syncthreads();
        if (tid < 128) {
            float m = red[tid * 16];
            #pragma unroll
            for (int j = 1; j < 16; j++) m = fmaxf(m, red[tid * 16 + j]);
            if (col0 + tid < N) atomicMax(&g_colmax[col0 + tid], encf(m));
        }
    } else {
        float rsm[8], csm[8];
        #pragma unroll
        for (int r = 0; r < 8; r++) rsm[r] = 0.f;
        #pragma unroll
        for (int c = 0; c < 8; c++) csm[c] = 0.f;
        #pragma unroll
        for (int r = 0; r < 8; r++) {
            int gr = row0 + ty * 8 + r;
            #pragma unroll
            for (int c = 0; c < 8; c++) {
                int gc = col0 + tx * 8 + c;
                bool valid = (gr < N) && (gc < N) &&
                             ((fr[ty * 8 + r] != fc[tx * 8 + c]) || (gr == gc));
                if (valid) {
                    float s = acc[r][c] * invT;
                    rsm[r] += __expf(s - rm_s[ty * 8 + r]);
                    csm[c] += __expf(s - cm_s[tx * 8 + c]);
                }
            }
        }
        #pragma unroll
        for (int r = 0; r < 8; r++) red[(ty * 8 + r) * 16 + tx] = rsm[r];
        __syncthreads();
        if (tid < 128) {
            float sm = 0.f;
            #pragma unroll
            for (int j = 0; j < 16; j++) sm += red[tid * 16 + j];
            if (row0 + tid < N) atomicAdd(&g_rowsum[row0 + tid], sm);
        }
        __syncthreads();
        #pragma unroll
        for (int c = 0; c < 8; c++) red[(tx * 8 + c) * 16 + ty] = csm[c];
        __syncthreads();
        if (tid < 128) {
            float sm = 0.f;
            #pragma unroll
            for (int j = 0; j < 16; j++) sm += red[tid * 16 + j];
            if (col0 + tid < N) atomicAdd(&g_colsum[col0 + tid], sm);
        }
    }
}

__global__ void finalize_kernel(float* out, int N) {
    __shared__ double sb[256];
    double acc = 0.0;
    for (int i = threadIdx.x; i < N; i += 256) {
        float rm = decf(g_rowmax[i]);
        float cm = decf(g_colmax[i]);
        acc += (double)(logf(g_rowsum[i]) + rm +
                        logf(g_colsum[i]) + cm - 2.0f * g_diag[i]);
    }
    sb[threadIdx.x] = acc;
    __syncthreads();
    for (int o = 128; o > 0; o >>= 1) {
        if (threadIdx.x < o) sb[threadIdx.x] += sb[threadIdx.x + o];
        __syncthreads();
    }
    if (threadIdx.x == 0) out[0] = (float)(sb[0] / (double)N);
}

extern "C" void kernel_launch(void* const* d_in, const int* in_sizes, int n_in,
                              void* d_out, int out_size) {
    const float* A    = (const float*)d_in[0];   // audio_embeds [N,E]
    const float* B    = (const float*)d_in[1];   // text_embeds  [N,E]
    const int*   fids = (const int*)d_in[2];     // [N]
    int N = in_sizes[2];
    int E = in_sizes[0] / N;
    float invT = 1.0f / TEMP;

    init_kernel<<<(N + 255) / 256, 256>>>(N);
    diag_kernel<<<(N * 32 + 255) / 256, 256>>>(A, B, N, E, invT);
    dim3 grid((N + 127) / 128, (N + 127) / 128);
    tile_kernel<0><<<grid, 256>>>(A, B, fids, N, E, invT);
    tile_kernel<1><<<grid, 256>>>(A, B, fids, N, E, invT);
    finalize_kernel<<<1, 256>>>((float*)d_out, N);
}

// round 3
// speedup vs baseline: 1.0020x; 1.0012x over previous
#include <cuda_runtime.h>

#define MAXN 8192
#define TEMP 0.07f

// ---- scratch (alloc-free per harness rules) ----
__device__ unsigned g_rowmax[MAXN];
__device__ unsigned g_colmax[MAXN];
__device__ float    g_rowsum[MAXN];
__device__ float    g_colsum[MAXN];
__device__ float    g_diag[MAXN];

// ---- ordered-uint encoding so atomicMax(unsigned) gives float max ----
static __device__ __forceinline__ unsigned encf(float f) {
    unsigned u = __float_as_uint(f);
    return (u & 0x80000000u) ? ~u : (u | 0x80000000u);
}
static __device__ __forceinline__ float decf(unsigned u) {
    return (u & 0x80000000u) ? __uint_as_float(u & 0x7FFFFFFFu)
                             : __uint_as_float(~u);
}

__global__ void init_kernel(int N) {
    int i = blockIdx.x * blockDim.x + threadIdx.x;
    if (i < N) {
        g_rowmax[i] = 0u;   // encodes below any real float (NaN zone) — always overwritten
        g_colmax[i] = 0u;
        g_rowsum[i] = 0.f;
        g_colsum[i] = 0.f;
    }
}

__global__ void diag_kernel(const float* __restrict__ A, const float* __restrict__ B,
                            int N, int E, float invT) {
    int w    = (blockIdx.x * blockDim.x + threadIdx.x) >> 5;
    int lane = threadIdx.x & 31;
    if (w >= N) return;
    float s = 0.f;
    for (int k = lane; k < E; k += 32)
        s += A[(size_t)w * E + k] * B[(size_t)w * E + k];
    #pragma unroll
    for (int o = 16; o > 0; o >>= 1) s += __shfl_xor_sync(0xffffffffu, s, o);
    if (lane == 0) g_diag[w] = s * invT;
}

// PASS 0: masked row/col max of S.   PASS 1: masked shifted-exp row/col sums.
template <int PASS>
__global__ void __launch_bounds__(256, 2)
tile_kernel(const float* __restrict__ A, const float* __restrict__ B,
            const int* __restrict__ fids, int N, int E, float invT) {
    __shared__ float As[16][132];       // +4 pad keeps float4 alignment, trims conflicts
    __shared__ float Bs[16][132];
    __shared__ int   fr[128], fc[128];
    __shared__ float red[128 * 16];
    __shared__ float rm_s[128], cm_s[128];

    const int tid  = threadIdx.x;
    const int tx   = tid & 15, ty = tid >> 4;
    const int row0 = blockIdx.y * 128, col0 = blockIdx.x * 128;

    if (tid < 128) {
        int rr = min(row0 + tid, N - 1);
        int cc = min(col0 + tid, N - 1);
        fr[tid] = fids[rr];
        fc[tid] = fids[cc];
        if (PASS == 1) {
            rm_s[tid] = decf(g_rowmax[rr]);
            cm_s[tid] = decf(g_colmax[cc]);
        }
    }

    float acc[8][8];
    #pragma unroll
    for (int r = 0; r < 8; r++)
        #pragma unroll
        for (int c = 0; c < 8; c++) acc[r][c] = 0.f;

    for (int k0 = 0; k0 < E; k0 += 16) {
        #pragma unroll
        for (int l = 0; l < 2; l++) {
            int idx = tid + l * 256;         // 0..511
            int r   = idx >> 2;              // tile row 0..127
            int k4  = (idx & 3) << 2;        // 0,4,8,12
            int ra  = min(row0 + r, N - 1);
            int rb  = min(col0 + r, N - 1);
            float4 va = *(const float4*)&A[(size_t)ra * E + k0 + k4];
            float4 vb = *(const float4*)&B[(size_t)rb * E + k0 + k4];
            As[k4 + 0][r] = va.x; As[k4 + 1][r] = va.y;
            As[k4 + 2][r] = va.z; As[k4 + 3][r] = va.w;
            Bs[k4 + 0][r] = vb.x; Bs[k4 + 1][r] = vb.y;
            Bs[k4 + 2][r] = vb.z; Bs[k4 + 3][r] = vb.w;
        }
        __syncthreads();
        #pragma unroll
        for (int k = 0; k < 16; k++) {
            float a[8], b[8];
            *(float4*)(a)     = *(const float4*)&As[k][ty * 8];
            *(float4*)(a + 4) = *(const float4*)&As[k][ty * 8 + 4];
            *(float4*)(b)     = *(const float4*)&Bs[k][tx * 8];
            *(float4*)(b + 4) = *(const float4*)&Bs[k][tx * 8 + 4];
            #pragma unroll
            for (int r = 0; r < 8; r++)
                #pragma unroll
                for (int c = 0; c < 8; c++)
                    acc[r][c] = fmaf(a[r], b[c], acc[r][c]);
        }
        __syncthreads();
    }

    if (PASS == 0) {
        float rmx[8], cmx[8];
        #pragma unroll
        for (int r = 0; r < 8; r++) rmx[r] = -3.4e38f;
        #pragma unroll
        for (int c = 0; c < 8; c++) cmx[c] = -3.4e38f;
        #pragma unroll
        for (int r = 0; r < 8; r++) {
            int gr = row0 + ty * 8 + r;
            #pragma unroll
            for (int c = 0; c < 8; c++) {
                int gc = col0 + tx * 8 + c;
                bool valid = (gr < N) && (gc < N) &&
                             ((fr[ty * 8 + r] != fc[tx * 8 + c]) || (gr == gc));
                float s = valid ? acc[r][c] * invT : -3.4e38f;
                rmx[r] = fmaxf(rmx[r], s);
                cmx[c] = fmaxf(cmx[c], s);
            }
        }
        #pragma unroll
        for (int r = 0; r < 8; r++) red[(ty * 8 + r) * 16 + tx] = rmx[r];
        __syncthreads();
        if (tid < 128) {
            float m = red[tid * 16];
            #pragma unroll
            for (int j = 1; j < 16; j++) m = fmaxf(m, red[tid * 16 + j]);
            if (row0 + tid < N) atomicMax(&g_rowmax[row0 + tid], encf(m));
        }
        __syncthreads();
        #pragma unroll
        for (int c = 0; c < 8; c++) red[(tx * 8 + c) * 16 + ty] = cmx[c];
        __syncthreads();
        if (tid < 128) {
            float m = red[tid * 16];
            #pragma unroll
            for (int j = 1; j < 16; j++) m = fmaxf(m, red[tid * 16 + j]);
            if (col0 + tid < N) atomicMax(&g_colmax[col0 + tid], encf(m));
        }
    } else {
        float rsm[8], csm[8];
        #pragma unroll
        for (int r = 0; r < 8; r++) rsm[r] = 0.f;
        #pragma unroll
        for (int c = 0; c < 8; c++) csm[c] = 0.f;
        #pragma unroll
        for (int r = 0; r < 8; r++) {
            int gr = row0 + ty * 8 + r;
            #pragma unroll
            for (int c = 0; c < 8; c++) {
                int gc = col0 + tx * 8 + c;
                bool valid = (gr < N) && (gc < N) &&
                             ((fr[ty * 8 + r] != fc[tx * 8 + c]) || (gr == gc));
                if (valid) {
                    float s = acc[r][c] * invT;
                    rsm[r] += __expf(s - rm_s[ty * 8 + r]);
                    csm[c] += __expf(s - cm_s[tx * 8 + c]);
                }
            }
        }
        #pragma unroll
        for (int r = 0; r < 8; r++) red[(ty * 8 + r) * 16 + tx] = rsm[r];
        __syncthreads();
        if (tid < 128) {
            float sm = 0.f;
            #pragma unroll
            for (int j = 0; j < 16; j++) sm += red[tid * 16 + j];
            if (row0 + tid < N) atomicAdd(&g_rowsum[row0 + tid], sm);
        }
        __syncthreads();
        #pragma unroll
        for (int c = 0; c < 8; c++) red[(tx * 8 + c) * 16 + ty] = csm[c];
        __syncthreads();
        if (tid < 128) {
            float sm = 0.f;
            #pragma unroll
            for (int j = 0; j < 16; j++) sm += red[tid * 16 + j];
            if (col0 + tid < N) atomicAdd(&g_colsum[col0 + tid], sm);
        }
    }
}

__global__ void finalize_kernel(float* out, int N) {
    __shared__ double sb[256];
    double acc = 0.0;
    for (int i = threadIdx.x; i < N; i += 256) {
        float rm = decf(g_rowmax[i]);
        float cm = decf(g_colmax[i]);
        acc += (double)(logf(g_rowsum[i]) + rm +
                        logf(g_colsum[i]) + cm - 2.0f * g_diag[i]);
    }
    sb[threadIdx.x] = acc;
    __syncthreads();
    for (int o = 128; o > 0; o >>= 1) {
        if (threadIdx.x < o) sb[threadIdx.x] += sb[threadIdx.x + o];
        __syncthreads();
    }
    if (threadIdx.x == 0) out[0] = (float)(sb[0] / (double)N);
}

extern "C" void kernel_launch(void* const* d_in, const int* in_sizes, int n_in,
                              void* d_out, int out_size) {
    const float* A    = (const float*)d_in[0];   // audio_embeds [N,E]
    const float* B    = (const float*)d_in[1];   // text_embeds  [N,E]
    const int*   fids = (const int*)d_in[2];     // [N]
    int N = in_sizes[2];
    int E = in_sizes[0] / N;
    float invT = 1.0f / TEMP;

    init_kernel<<<(N + 255) / 256, 256>>>(N);
    diag_kernel<<<(N * 32 + 255) / 256, 256>>>(A, B, N, E, invT);
    dim3 grid((N + 127) / 128, (N + 127) / 128);
    tile_kernel<0><<<grid, 256>>>(A, B, fids, N, E, invT);
    tile_kernel<1><<<grid, 256>>>(A, B, fids, N, E, invT);
    finalize_kernel<<<1, 256>>>((float*)d_out, N);
}